// round 12
// baseline (speedup 1.0000x reference)
#include <cuda_runtime.h>
#include <cuda_fp16.h>
#include <math.h>

// Problem constants
#define S_      8
#define U_      8
#define KSTEPS  12
#define NEG     17
#define ZD      64
#define CD      256
#define T_      1140
#define LEN     1128
#define SU      64              // S_*U_
#define MROWS   (SU*LEN)        // 72192
#define NTILES  (MROWS/128)     // 564
#define WCSTR   68              // smem Wc row stride (floats)
#define SAS2    264             // smem A/B row stride in halves (528B = 33*16B, ldmatrix conflict-free)

#define SA_BYTES   (128 * SAS2 * 2)                    // 67584
#define OVL_BYTES  (128 * WCSTR * 4)                   // 34816 (>= 64*SAS2*2 = 33792)
#define SMEM_TOTAL (SA_BYTES + OVL_BYTES)              // 102400

__device__ float g_loss_sum[KSTEPS];
__device__ float g_acc_sum[KSTEPS];
__device__ __half g_zh[(size_t)SU * T_ * ZD];          // fp16 z copy (9.3 MB)
__device__ __half g_Wh[(size_t)KSTEPS * ZD * CD];      // fp16 W copy (393 KB)

// -------------------------------------------------------------------------
__global__ void zero_sums_kernel() {
    int t = threadIdx.x;
    if (t < KSTEPS) { g_loss_sum[t] = 0.f; g_acc_sum[t] = 0.f; }
}

__global__ void convert_z_kernel(const float* __restrict__ z) {
    size_t i = (size_t)blockIdx.x * blockDim.x + threadIdx.x;
    const size_t n4 = (size_t)SU * T_ * ZD / 4;
    if (i < n4) {
        float4 v = ((const float4*)z)[i];
        __half2 h0 = __floats2half2_rn(v.x, v.y);
        __half2 h1 = __floats2half2_rn(v.z, v.w);
        uint2 o; o.x = *(unsigned*)&h0; o.y = *(unsigned*)&h1;
        ((uint2*)g_zh)[i] = o;
    }
}

__global__ void convert_W_kernel(const float* __restrict__ W) {
    size_t i = (size_t)blockIdx.x * blockDim.x + threadIdx.x;
    const size_t n4 = (size_t)KSTEPS * ZD * CD / 4;
    if (i < n4) {
        float4 v = ((const float4*)W)[i];
        __half2 h0 = __floats2half2_rn(v.x, v.y);
        __half2 h1 = __floats2half2_rn(v.z, v.w);
        uint2 o; o.x = *(unsigned*)&h0; o.y = *(unsigned*)&h1;
        ((uint2*)g_Wh)[i] = o;
    }
}

// -------------------------------------------------------------------------
__device__ __forceinline__ uint2 pack_h4(float4 v) {
    __half2 h0 = __floats2half2_rn(v.x, v.y);
    __half2 h1 = __floats2half2_rn(v.z, v.w);
    uint2 o; o.x = *(unsigned*)&h0; o.y = *(unsigned*)&h1;
    return o;
}

__device__ __forceinline__ void ldmx4(unsigned* r, unsigned addr) {
    asm volatile("ldmatrix.sync.aligned.m8n8.x4.shared.b16 {%0,%1,%2,%3}, [%4];"
                 : "=r"(r[0]), "=r"(r[1]), "=r"(r[2]), "=r"(r[3]) : "r"(addr));
}

__device__ __forceinline__ void mma16816(float* c, const unsigned* a,
                                         unsigned b0, unsigned b1) {
    asm volatile(
        "mma.sync.aligned.m16n8k16.row.col.f32.f16.f16.f32 "
        "{%0,%1,%2,%3}, {%4,%5,%6,%7}, {%8,%9}, {%0,%1,%2,%3};\n"
        : "+f"(c[0]), "+f"(c[1]), "+f"(c[2]), "+f"(c[3])
        : "r"(a[0]), "r"(a[1]), "r"(a[2]), "r"(a[3]), "r"(b0), "r"(b1));
}

// -------------------------------------------------------------------------
// One CTA per 128-row m-tile. fp16 A tile (c rows) resident in smem across
// ALL 12 k's; per k: load W[k] fp16, GEMM (ldmatrix + m16n8k16), epilogue
// to sWc (overlays sB), score (quad-parallel, fp16 neg gathers).
__global__ __launch_bounds__(256, 2)
void fused_kernel(const float* __restrict__ z,
                  const float* __restrict__ c,
                  const float* __restrict__ bias,
                  const int* __restrict__ batch_index,
                  const int* __restrict__ seq_index) {
    extern __shared__ __align__(16) char smem_u[];
    __shared__ float s_lossArr[KSTEPS], s_accArr[KSTEPS];

    __half* sA  = (__half*)smem_u;                 // [128][SAS2]
    __half* sB  = (__half*)(smem_u + SA_BYTES);    // [64][SAS2]  (per-k)
    float*  sWc = (float*)(smem_u + SA_BYTES);     // [128][WCSTR] overlays sB

    const int m0 = blockIdx.x * 128;

    const int tid  = threadIdx.x;
    const int warp = tid >> 5;
    const int lane = tid & 31;
    const int grp  = lane >> 2;
    const int tig  = lane & 3;
    const int mw   = warp * 16;

    if (tid < KSTEPS) { s_lossArr[tid] = 0.f; s_accArr[tid] = 0.f; }

    // ---------------- A tile load (ONCE): c f32 -> fp16 smem ----------------
    const int lr  = tid >> 4;               // 0..15
    const int c16 = tid & 15;
    {
        const float* arow[8];
#pragma unroll
        for (int p = 0; p < 8; p++) {
            int m  = m0 + lr + 16 * p;
            int su = m / LEN;
            int l  = m - su * LEN;
            arow[p] = c + ((size_t)(su * T_ + l)) * CD + c16 * 4;
        }
#pragma unroll
        for (int ch = 0; ch < 4; ch++) {
#pragma unroll
            for (int p = 0; p < 8; p++) {
                float4 v = *(const float4*)(arow[p] + ch * 64);
                *(uint2*)&sA[(lr + 16 * p) * SAS2 + ch * 64 + c16 * 4] = pack_h4(v);
            }
        }
    }

    // ldmatrix lane addresses
    const unsigned sA_b = (unsigned)__cvta_generic_to_shared(sA);
    const unsigned sB_b = (unsigned)__cvta_generic_to_shared(sB);
    const unsigned laneA = sA_b + (((mw + (lane & 15)) * SAS2 + ((lane >> 4) << 3)) << 1);
    const unsigned laneB = sB_b + ((((lane & 15)) * SAS2 + ((lane >> 4) << 3)) << 1);

    // B loader indices: 4 threads per row, 64 halves each
    const int bn_row = tid >> 2;            // 0..63
    const int bq     = tid & 3;             // 0..3

    const int quad = lane >> 3;
    const int lq   = lane & 7;

    __syncthreads();                        // A tile ready

    for (int k = 0; k < KSTEPS; k++) {
        // ---------------- B tile: g_Wh[k] -> sB ----------------
        {
            const __half* wsrc = g_Wh + (size_t)k * ZD * CD + bn_row * CD + bq * 64;
            __half* wdst = sB + bn_row * SAS2 + bq * 64;
#pragma unroll
            for (int i = 0; i < 8; i++)
                *(uint4*)(wdst + 8 * i) = *(const uint4*)(wsrc + 8 * i);
        }
        __syncthreads();

        // ---------------- GEMM ----------------
        float acc[8][4];
#pragma unroll
        for (int j = 0; j < 8; j++)
#pragma unroll
            for (int i = 0; i < 4; i++) acc[j][i] = 0.f;

#pragma unroll
        for (int ks = 0; ks < 16; ks++) {
            unsigned a[4];
            ldmx4(a, laneA + (ks << 5));
#pragma unroll
            for (int j2 = 0; j2 < 4; j2++) {
                unsigned bf[4];
                ldmx4(bf, laneB + (unsigned)(j2 * 16 * SAS2 * 2) + (ks << 5));
                mma16816(acc[2 * j2],     a, bf[0], bf[2]);
                mma16816(acc[2 * j2 + 1], a, bf[1], bf[3]);
            }
        }
        __syncthreads();                    // GEMM reads done before sWc overwrite

        // ---------------- epilogue: bias + park Wc ----------------
#pragma unroll
        for (int j = 0; j < 8; j++) {
            const int n = 8 * j + 2 * tig;
            float2 bb = *(const float2*)(bias + k * ZD + n);
            float2 o0, o1;
            o0.x = acc[j][0] + bb.x; o0.y = acc[j][1] + bb.y;
            o1.x = acc[j][2] + bb.x; o1.y = acc[j][3] + bb.y;
            *(float2*)(sWc + (size_t)(mw + grp) * WCSTR + n)     = o0;
            *(float2*)(sWc + (size_t)(mw + grp + 8) * WCSTR + n) = o1;
        }
        __syncthreads();

        // ---------------- scoring (quad-parallel) ----------------
        float warp_loss = 0.f, warp_acc = 0.f;

#pragma unroll
        for (int it = 0; it < 4; it++) {
            const int r  = mw + it * 4 + quad;
            const int m  = m0 + r;
            const int su = m / LEN;
            const int l  = m - su * LEN;
            const int s  = su >> 3;
            const int u  = su & 7;

            const float4* w4 = (const float4*)(sWc + (size_t)r * WCSTR + lq * 8);
            float4 w0 = w4[0], w1 = w4[1];

            const float4* zp = (const float4*)(z +
                (size_t)(su * T_ + (l + k + 1)) * ZD + lq * 8);
            float4 z0 = zp[0], z1 = zp[1];

            float p[18];
            {
                float sum = z0.x * w0.x;
                sum = fmaf(z0.y, w0.y, sum);
                sum = fmaf(z0.z, w0.z, sum);
                sum = fmaf(z0.w, w0.w, sum);
                sum = fmaf(z1.x, w1.x, sum);
                sum = fmaf(z1.y, w1.y, sum);
                sum = fmaf(z1.z, w1.z, sum);
                sum = fmaf(z1.w, w1.w, sum);
                p[0] = sum;
            }

            const int* bi = batch_index + (k * U_ + u) * NEG;
            const int* si = seq_index + ((size_t)((k * S_ + s) * U_ + u) * NEG) * LEN + l;
            int bn_r[3], sn_r[3];
#pragma unroll
            for (int j = 0; j < 3; j++) {
                int n = lq + 8 * j;
                if (n < NEG) {
                    bn_r[j] = __ldg(bi + n);
                    sn_r[j] = __ldg(si + (size_t)n * LEN);
                } else { bn_r[j] = 0; sn_r[j] = 0; }
            }

#pragma unroll
            for (int n = 0; n < NEG; n++) {
                int bn = __shfl_sync(0xffffffffu, bn_r[n >> 3], n & 7, 8);
                int sn = __shfl_sync(0xffffffffu, sn_r[n >> 3], n & 7, 8);
                const uint4* zn = (const uint4*)((const __half*)g_zh +
                    (size_t)((s * U_ + bn) * T_ + (k + 1 + sn)) * ZD + lq * 8);
                uint4 raw = *zn;
                __half2 h0 = *(__half2*)&raw.x;
                __half2 h1 = *(__half2*)&raw.y;
                __half2 h2 = *(__half2*)&raw.z;
                __half2 h3 = *(__half2*)&raw.w;
                float2 a0 = __half22float2(h0);
                float2 a1 = __half22float2(h1);
                float2 a2 = __half22float2(h2);
                float2 a3 = __half22float2(h3);
                float sum = a0.x * w0.x;
                sum = fmaf(a0.y, w0.y, sum);
                sum = fmaf(a1.x, w0.z, sum);
                sum = fmaf(a1.y, w0.w, sum);
                sum = fmaf(a2.x, w1.x, sum);
                sum = fmaf(a2.y, w1.y, sum);
                sum = fmaf(a3.x, w1.z, sum);
                sum = fmaf(a3.y, w1.w, sum);
                p[1 + n] = sum;
            }

#pragma unroll
            for (int off = 4; off >= 1; off >>= 1) {
#pragma unroll
                for (int n = 0; n < 18; n++)
                    p[n] += __shfl_xor_sync(0xffffffffu, p[n], off);
            }

            if (lq == 0) {
                float f0 = p[0] * 0.125f;
                float mxn = p[1];
#pragma unroll
                for (int n = 2; n < 18; n++) mxn = fmaxf(mxn, p[n]);
                mxn *= 0.125f;
                float mx = fmaxf(f0, mxn);
                float se = __expf(f0 - mx);
#pragma unroll
                for (int n = 1; n < 18; n++) se += __expf(p[n] * 0.125f - mx);
                warp_loss += (mx + __logf(se)) - f0;
                warp_acc  += (f0 >= mxn) ? 1.f : 0.f;
            }
        }

        warp_loss += __shfl_xor_sync(0xffffffffu, warp_loss, 8);
        warp_loss += __shfl_xor_sync(0xffffffffu, warp_loss, 16);
        warp_acc  += __shfl_xor_sync(0xffffffffu, warp_acc, 8);
        warp_acc  += __shfl_xor_sync(0xffffffffu, warp_acc, 16);

        if (lane == 0) {
            atomicAdd(&s_lossArr[k], warp_loss);
            atomicAdd(&s_accArr[k], warp_acc);
        }
        __syncthreads();                    // scoring reads done before next sB load
    }

    if (tid < KSTEPS) {
        atomicAdd(&g_loss_sum[tid], s_lossArr[tid]);
        atomicAdd(&g_acc_sum[tid], s_accArr[tid]);
    }
}

// -------------------------------------------------------------------------
__global__ void finalize_kernel(float* __restrict__ out, int out_size) {
    __shared__ float sl[KSTEPS];
    int t = threadIdx.x;
    const float inv = 1.f / (float)(SU * LEN);
    if (t < KSTEPS) {
        sl[t] = g_loss_sum[t] * inv;
        if (1 + t < out_size) out[1 + t] = g_acc_sum[t] * inv;
    }
    __syncthreads();
    if (t == 0 && out_size > 0) {
        float sum = 0.f;
        for (int i = 0; i < KSTEPS; i++) sum += sl[i];
        out[0] = sum * (1.f / (float)KSTEPS);
    }
    for (int i = 13 + t; i < out_size; i += blockDim.x) out[i] = 0.f;
}

// -------------------------------------------------------------------------
extern "C" void kernel_launch(void* const* d_in, const int* in_sizes, int n_in,
                              void* d_out, int out_size) {
    const float* z           = (const float*)d_in[0];
    const float* c           = (const float*)d_in[1];
    const float* W           = (const float*)d_in[2];
    const float* b           = (const float*)d_in[3];
    const int*   batch_index = (const int*)d_in[4];
    const int*   seq_index   = (const int*)d_in[5];

    cudaFuncSetAttribute(fused_kernel,
                         cudaFuncAttributeMaxDynamicSharedMemorySize, SMEM_TOTAL);

    zero_sums_kernel<<<1, 32>>>();

    const size_t nz4 = (size_t)SU * T_ * ZD / 4;
    convert_z_kernel<<<(unsigned)((nz4 + 255) / 256), 256>>>(z);
    const size_t nw4 = (size_t)KSTEPS * ZD * CD / 4;
    convert_W_kernel<<<(unsigned)((nw4 + 255) / 256), 256>>>(W);

    fused_kernel<<<NTILES, 256, SMEM_TOTAL>>>(z, c, b, batch_index, seq_index);
    finalize_kernel<<<1, 64>>>((float*)d_out, out_size);
}

// round 14
// speedup vs baseline: 1.0837x; 1.0837x over previous
#include <cuda_runtime.h>
#include <cuda_fp16.h>
#include <math.h>

// Problem constants
#define S_      8
#define U_      8
#define KSTEPS  12
#define NEG     17
#define ZD      64
#define CD      256
#define T_      1140
#define LEN     1128
#define SU      64              // S_*U_
#define MROWS   (SU*LEN)        // 72192
#define NTILES  (MROWS/128)     // 564
#define WCSTR   72              // smem Wc row stride (floats)
#define CK      64              // K-chunk (fp16 GEMM)
#define SAS     72              // smem A/B row stride in halves

// smem layout (dynamic): [0,36864) = sA(18432)+sB(9216) overlaid by sWc(36864)
//                        [36864, +8704) sSn ; [45568, +8704) sBn
#define UNION_BYTES 36864
#define IDX_INTS    (NEG * 128)                 // 2176
#define SMEM_TOTAL  (UNION_BYTES + 2 * IDX_INTS * 4)   // 54272

__device__ float g_loss_sum[KSTEPS];
__device__ float g_acc_sum[KSTEPS];
__device__ __half g_zh[(size_t)SU * T_ * ZD];          // fp16 z copy (9.3 MB)
__device__ __half g_Wh[(size_t)KSTEPS * ZD * CD];      // fp16 W copy (393 KB)

// -------------------------------------------------------------------------
__global__ void zero_sums_kernel() {
    int t = threadIdx.x;
    if (t < KSTEPS) { g_loss_sum[t] = 0.f; g_acc_sum[t] = 0.f; }
}

__global__ void convert_z_kernel(const float* __restrict__ z) {
    size_t i = (size_t)blockIdx.x * blockDim.x + threadIdx.x;
    const size_t n4 = (size_t)SU * T_ * ZD / 4;
    if (i < n4) {
        float4 v = ((const float4*)z)[i];
        __half2 h0 = __floats2half2_rn(v.x, v.y);
        __half2 h1 = __floats2half2_rn(v.z, v.w);
        uint2 o; o.x = *(unsigned*)&h0; o.y = *(unsigned*)&h1;
        ((uint2*)g_zh)[i] = o;
    }
}

__global__ void convert_W_kernel(const float* __restrict__ W) {
    size_t i = (size_t)blockIdx.x * blockDim.x + threadIdx.x;
    const size_t n4 = (size_t)KSTEPS * ZD * CD / 4;
    if (i < n4) {
        float4 v = ((const float4*)W)[i];
        __half2 h0 = __floats2half2_rn(v.x, v.y);
        __half2 h1 = __floats2half2_rn(v.z, v.w);
        uint2 o; o.x = *(unsigned*)&h0; o.y = *(unsigned*)&h1;
        ((uint2*)g_Wh)[i] = o;
    }
}

// -------------------------------------------------------------------------
__device__ __forceinline__ uint2 pack_h4(float4 v) {
    __half2 h0 = __floats2half2_rn(v.x, v.y);
    __half2 h1 = __floats2half2_rn(v.z, v.w);
    uint2 o; o.x = *(unsigned*)&h0; o.y = *(unsigned*)&h1;
    return o;
}

__device__ __forceinline__ void ldmx4(unsigned* r, unsigned addr) {
    asm volatile("ldmatrix.sync.aligned.m8n8.x4.shared.b16 {%0,%1,%2,%3}, [%4];"
                 : "=r"(r[0]), "=r"(r[1]), "=r"(r[2]), "=r"(r[3]) : "r"(addr));
}

__device__ __forceinline__ void mma16816(float* c, const unsigned* a,
                                         unsigned b0, unsigned b1) {
    asm volatile(
        "mma.sync.aligned.m16n8k16.row.col.f32.f16.f16.f32 "
        "{%0,%1,%2,%3}, {%4,%5,%6,%7}, {%8,%9}, {%0,%1,%2,%3};\n"
        : "+f"(c[0]), "+f"(c[1]), "+f"(c[2]), "+f"(c[3])
        : "r"(a[0]), "r"(a[1]), "r"(a[2]), "r"(a[3]), "r"(b0), "r"(b1));
}

// -------------------------------------------------------------------------
// CTA = one (128-row m-tile, k). fp16 ldmatrix GEMM -> sWc in smem -> score.
// Indices staged coalesced into smem; B tile loaded from fp16 g_Wh.
__global__ __launch_bounds__(256, 2)
void fused_kernel(const float* __restrict__ z,
                  const float* __restrict__ c,
                  const float* __restrict__ bias,
                  const int* __restrict__ batch_index,
                  const int* __restrict__ seq_index) {
    extern __shared__ __align__(16) char smem_u[];
    __shared__ float s_loss, s_acc;

    __half* sA  = (__half*)smem_u;                  // [128][SAS]
    __half* sB  = sA + 128 * SAS;                   // [64][SAS]
    float*  sWc = (float*)smem_u;                   // [128][WCSTR] overlays
    int*    sSn = (int*)(smem_u + UNION_BYTES);     // [NEG][128]
    int*    sBn = sSn + IDX_INTS;                   // [NEG][128]

    const int bx = blockIdx.x;
    const int k  = bx % KSTEPS;             // k fastest -> c tile L2 reuse
    const int m0 = (bx / KSTEPS) * 128;

    const int tid  = threadIdx.x;
    const int warp = tid >> 5;
    const int lane = tid & 31;
    const int grp  = lane >> 2;
    const int tig  = lane & 3;
    const int mw   = warp * 16;

    if (tid == 0) { s_loss = 0.f; s_acc = 0.f; }

    // ---------------- stage indices (coalesced; overlaps GEMM loads) -------
#pragma unroll
    for (int i = 0; i < 9; i++) {
        int idx = tid + 256 * i;
        if (idx < IDX_INTS) {
            int n  = idx >> 7;
            int rr = idx & 127;
            int m  = m0 + rr;
            int su = m / LEN;
            int l  = m - su * LEN;
            int s  = su >> 3;
            int u  = su & 7;
            sBn[idx] = __ldg(batch_index + (k * U_ + u) * NEG + n);
            sSn[idx] = __ldg(seq_index +
                ((size_t)((k * S_ + s) * U_ + u) * NEG + n) * LEN + l);
        }
    }

    // ---------------- GEMM phase (fp16 ldmatrix + mma.m16n8k16) ------------
    const int lr  = tid >> 4;               // 0..15 loader row-in-pass
    const int c16 = tid & 15;

    const float* arow[8];
#pragma unroll
    for (int p = 0; p < 8; p++) {
        int m  = m0 + lr + 16 * p;
        int su = m / LEN;
        int l  = m - su * LEN;
        arow[p] = c + ((size_t)(su * T_ + l)) * CD + c16 * 4;
    }

    // B loader: 4 threads per row, 32 halves each (2 uint4)
    const int brow_i = tid >> 2;            // 0..63
    const int bq     = tid & 3;             // 0..3
    const __half* wsrc = g_Wh + (size_t)k * ZD * CD + brow_i * CD + bq * 16;

    const unsigned sA_b = (unsigned)__cvta_generic_to_shared(sA);
    const unsigned sB_b = (unsigned)__cvta_generic_to_shared(sB);
    const unsigned laneA = sA_b + (((mw + (lane & 15)) * SAS + ((lane >> 4) << 3)) << 1);
    const unsigned laneB = sB_b + ((((lane & 15)) * SAS + ((lane >> 4) << 3)) << 1);

    float acc[8][4];
#pragma unroll
    for (int j = 0; j < 8; j++)
#pragma unroll
        for (int i = 0; i < 4; i++) acc[j][i] = 0.f;

    for (int kk = 0; kk < CD; kk += CK) {
        // A: c fp32 -> fp16 smem (8 passes of 16 rows)
#pragma unroll
        for (int p = 0; p < 8; p++) {
            float4 v = *(const float4*)(arow[p] + kk);
            *(uint2*)&sA[(lr + 16 * p) * SAS + c16 * 4] = pack_h4(v);
        }
        // B: fp16 g_Wh -> smem. Row = brow_i, halves [bq*16, bq*16+16) of chunk
        {
            const __half* ws = wsrc + kk;
            __half* wd = sB + brow_i * SAS + bq * 16;
            *(uint4*)(wd)     = *(const uint4*)(ws);
            *(uint4*)(wd + 8) = *(const uint4*)(ws + 8);
        }
        __syncthreads();

#pragma unroll
        for (int ks = 0; ks < 4; ks++) {
            unsigned a[4];
            ldmx4(a, laneA + (ks << 5));
#pragma unroll
            for (int j2 = 0; j2 < 4; j2++) {
                unsigned bf[4];
                ldmx4(bf, laneB + (unsigned)(j2 * 16 * SAS * 2) + (ks << 5));
                mma16816(acc[2 * j2],     a, bf[0], bf[2]);
                mma16816(acc[2 * j2 + 1], a, bf[1], bf[3]);
            }
        }
        __syncthreads();
    }

    // ---------------- epilogue: bias + park Wc tile in smem ----------------
#pragma unroll
    for (int j = 0; j < 8; j++) {
        const int n = 8 * j + 2 * tig;
        float2 bb = *(const float2*)(bias + k * ZD + n);
        float2 o0, o1;
        o0.x = acc[j][0] + bb.x; o0.y = acc[j][1] + bb.y;
        o1.x = acc[j][2] + bb.x; o1.y = acc[j][3] + bb.y;
        *(float2*)(sWc + (size_t)(mw + grp) * WCSTR + n)     = o0;
        *(float2*)(sWc + (size_t)(mw + grp + 8) * WCSTR + n) = o1;
    }
    __syncthreads();

    // ---------------- scoring phase: quad-parallel, smem indices -----------
    const int quad = lane >> 3;
    const int lq   = lane & 7;

    float warp_loss = 0.f, warp_acc = 0.f;

#pragma unroll
    for (int it = 0; it < 4; it++) {
        const int r  = mw + it * 4 + quad;
        const int m  = m0 + r;
        const int su = m / LEN;
        const int l  = m - su * LEN;
        const int s  = su >> 3;

        const float4* w4 = (const float4*)(sWc + (size_t)r * WCSTR + lq * 8);
        float4 w0 = w4[0], w1 = w4[1];

        const float4* zp = (const float4*)(z +
            (size_t)(su * T_ + (l + k + 1)) * ZD + lq * 8);
        float4 z0 = zp[0], z1 = zp[1];

        float p[18];
        {
            float sum = z0.x * w0.x;
            sum = fmaf(z0.y, w0.y, sum);
            sum = fmaf(z0.z, w0.z, sum);
            sum = fmaf(z0.w, w0.w, sum);
            sum = fmaf(z1.x, w1.x, sum);
            sum = fmaf(z1.y, w1.y, sum);
            sum = fmaf(z1.z, w1.z, sum);
            sum = fmaf(z1.w, w1.w, sum);
            p[0] = sum;
        }

#pragma unroll
        for (int n = 0; n < NEG; n++) {
            int bn = sBn[(n << 7) + r];     // LDS broadcast within quad
            int sn = sSn[(n << 7) + r];
            const uint4* zn = (const uint4*)((const __half*)g_zh +
                (size_t)((s * U_ + bn) * T_ + (k + 1 + sn)) * ZD + lq * 8);
            uint4 raw = *zn;
            __half2 h0 = *(__half2*)&raw.x;
            __half2 h1 = *(__half2*)&raw.y;
            __half2 h2 = *(__half2*)&raw.z;
            __half2 h3 = *(__half2*)&raw.w;
            float2 a0 = __half22float2(h0);
            float2 a1 = __half22float2(h1);
            float2 a2 = __half22float2(h2);
            float2 a3 = __half22float2(h3);
            float sum = a0.x * w0.x;
            sum = fmaf(a0.y, w0.y, sum);
            sum = fmaf(a1.x, w0.z, sum);
            sum = fmaf(a1.y, w0.w, sum);
            sum = fmaf(a2.x, w1.x, sum);
            sum = fmaf(a2.y, w1.y, sum);
            sum = fmaf(a3.x, w1.z, sum);
            sum = fmaf(a3.y, w1.w, sum);
            p[1 + n] = sum;
        }

#pragma unroll
        for (int off = 4; off >= 1; off >>= 1) {
#pragma unroll
            for (int n = 0; n < 18; n++)
                p[n] += __shfl_xor_sync(0xffffffffu, p[n], off);
        }

        if (lq == 0) {
            float f0 = p[0] * 0.125f;
            float mxn = p[1];
#pragma unroll
            for (int n = 2; n < 18; n++) mxn = fmaxf(mxn, p[n]);
            mxn *= 0.125f;
            float mx = fmaxf(f0, mxn);
            float se = __expf(f0 - mx);
#pragma unroll
            for (int n = 1; n < 18; n++) se += __expf(p[n] * 0.125f - mx);
            warp_loss += (mx + __logf(se)) - f0;
            warp_acc  += (f0 >= mxn) ? 1.f : 0.f;
        }
    }

    warp_loss += __shfl_xor_sync(0xffffffffu, warp_loss, 8);
    warp_loss += __shfl_xor_sync(0xffffffffu, warp_loss, 16);
    warp_acc  += __shfl_xor_sync(0xffffffffu, warp_acc, 8);
    warp_acc  += __shfl_xor_sync(0xffffffffu, warp_acc, 16);

    if (lane == 0) {
        atomicAdd(&s_loss, warp_loss);
        atomicAdd(&s_acc, warp_acc);
    }
    __syncthreads();
    if (tid == 0) {
        atomicAdd(&g_loss_sum[k], s_loss);
        atomicAdd(&g_acc_sum[k], s_acc);
    }
}

// -------------------------------------------------------------------------
__global__ void finalize_kernel(float* __restrict__ out, int out_size) {
    __shared__ float sl[KSTEPS];
    int t = threadIdx.x;
    const float inv = 1.f / (float)(SU * LEN);
    if (t < KSTEPS) {
        sl[t] = g_loss_sum[t] * inv;
        if (1 + t < out_size) out[1 + t] = g_acc_sum[t] * inv;
    }
    __syncthreads();
    if (t == 0 && out_size > 0) {
        float sum = 0.f;
        for (int i = 0; i < KSTEPS; i++) sum += sl[i];
        out[0] = sum * (1.f / (float)KSTEPS);
    }
    for (int i = 13 + t; i < out_size; i += blockDim.x) out[i] = 0.f;
}

// -------------------------------------------------------------------------
extern "C" void kernel_launch(void* const* d_in, const int* in_sizes, int n_in,
                              void* d_out, int out_size) {
    const float* z           = (const float*)d_in[0];
    const float* c           = (const float*)d_in[1];
    const float* W           = (const float*)d_in[2];
    const float* b           = (const float*)d_in[3];
    const int*   batch_index = (const int*)d_in[4];
    const int*   seq_index   = (const int*)d_in[5];

    cudaFuncSetAttribute(fused_kernel,
                         cudaFuncAttributeMaxDynamicSharedMemorySize, SMEM_TOTAL);

    zero_sums_kernel<<<1, 32>>>();

    const size_t nz4 = (size_t)SU * T_ * ZD / 4;
    convert_z_kernel<<<(unsigned)((nz4 + 255) / 256), 256>>>(z);
    const size_t nw4 = (size_t)KSTEPS * ZD * CD / 4;
    convert_W_kernel<<<(unsigned)((nw4 + 255) / 256), 256>>>(W);

    fused_kernel<<<NTILES * KSTEPS, 256, SMEM_TOTAL>>>(z, c, b, batch_index, seq_index);
    finalize_kernel<<<1, 64>>>((float*)d_out, out_size);
}

// round 15
// speedup vs baseline: 1.2100x; 1.1166x over previous
#include <cuda_runtime.h>
#include <cuda_fp16.h>
#include <math.h>

// Problem constants
#define S_      8
#define U_      8
#define KSTEPS  12
#define NEG     17
#define ZD      64
#define CD      256
#define T_      1140
#define LEN     1128
#define SU      64              // S_*U_
#define MROWS   (SU*LEN)        // 72192
#define NTILES  (MROWS/128)     // 564
#define WCSTR   72              // smem Wc row stride (floats)
#define CK      64              // K-chunk (fp16 GEMM)
#define SAS     72              // smem A/B row stride in halves (144B: ldmatrix conflict-free)

__device__ float g_loss_sum[KSTEPS];
__device__ float g_acc_sum[KSTEPS];
__device__ __half g_zh[(size_t)SU * T_ * ZD];   // fp16 copy of z (9.3 MB)

// -------------------------------------------------------------------------
__global__ void zero_sums_kernel() {
    int t = threadIdx.x;
    if (t < KSTEPS) { g_loss_sum[t] = 0.f; g_acc_sum[t] = 0.f; }
}

// z -> fp16 (once per launch; deterministic)
__global__ void convert_z_kernel(const float* __restrict__ z) {
    size_t i = (size_t)blockIdx.x * blockDim.x + threadIdx.x;   // one float4
    const size_t n4 = (size_t)SU * T_ * ZD / 4;
    if (i < n4) {
        float4 v = ((const float4*)z)[i];
        __half2 h0 = __floats2half2_rn(v.x, v.y);
        __half2 h1 = __floats2half2_rn(v.z, v.w);
        uint2 o;
        o.x = *(unsigned*)&h0;
        o.y = *(unsigned*)&h1;
        ((uint2*)g_zh)[i] = o;
    }
}

// -------------------------------------------------------------------------
__device__ __forceinline__ uint2 pack_h4(float4 v) {
    __half2 h0 = __floats2half2_rn(v.x, v.y);
    __half2 h1 = __floats2half2_rn(v.z, v.w);
    uint2 o;
    o.x = *(unsigned*)&h0;
    o.y = *(unsigned*)&h1;
    return o;
}

__device__ __forceinline__ void ldmx4(unsigned* r, unsigned addr) {
    asm volatile("ldmatrix.sync.aligned.m8n8.x4.shared.b16 {%0,%1,%2,%3}, [%4];"
                 : "=r"(r[0]), "=r"(r[1]), "=r"(r[2]), "=r"(r[3]) : "r"(addr));
}

__device__ __forceinline__ void mma16816(float* c, const unsigned* a,
                                         unsigned b0, unsigned b1) {
    asm volatile(
        "mma.sync.aligned.m16n8k16.row.col.f32.f16.f16.f32 "
        "{%0,%1,%2,%3}, {%4,%5,%6,%7}, {%8,%9}, {%0,%1,%2,%3};\n"
        : "+f"(c[0]), "+f"(c[1]), "+f"(c[2]), "+f"(c[3])
        : "r"(a[0]), "r"(a[1]), "r"(a[2]), "r"(a[3]), "r"(b0), "r"(b1));
}

// -------------------------------------------------------------------------
// Fused (R11 structure): per CTA one 128x64 Wc tile via fp16 ldmatrix mma
// into smem, then quad-parallel scoring with fp16 neg gathers.
// R15 change: combined gather offsets precomputed at preload; one shuffle
// + shift/add per neg instead of two shuffles + 5-op address chain.
__global__ __launch_bounds__(256, 2)
void fused_kernel(const float* __restrict__ z,
                  const float* __restrict__ c,
                  const float* __restrict__ W,
                  const float* __restrict__ bias,
                  const int* __restrict__ batch_index,
                  const int* __restrict__ seq_index) {
    __shared__ __align__(16) char smem_u[128 * WCSTR * 4];   // 36864 B union
    __shared__ float s_loss, s_acc;

    __half* sA  = (__half*)smem_u;          // [128][SAS] = 18432 B
    __half* sB  = sA + 128 * SAS;           // [64][SAS]  =  9216 B
    float*  sWc = (float*)smem_u;           // [128][WCSTR] overlays later

    const int bx = blockIdx.x;
    const int k  = bx % KSTEPS;             // k fastest -> c tile L2 reuse
    const int m0 = (bx / KSTEPS) * 128;

    const int tid  = threadIdx.x;
    const int warp = tid >> 5;
    const int lane = tid & 31;
    const int grp  = lane >> 2;             // 0..7 (mma C rows)
    const int tig  = lane & 3;              // 0..3
    const int mw   = warp * 16;

    if (tid == 0) { s_loss = 0.f; s_acc = 0.f; }

    // ---------------- GEMM phase (fp16 ldmatrix + mma.m16n8k16) ------------
    const int lr  = tid >> 4;               // 0..15 loader row-in-pass
    const int c16 = tid & 15;               // float4 col within 64-wide chunk

    const float* arow[8];
#pragma unroll
    for (int p = 0; p < 8; p++) {
        int m  = m0 + lr + 16 * p;
        int su = m / LEN;
        int l  = m - su * LEN;
        arow[p] = c + ((size_t)(su * T_ + l)) * CD + c16 * 4;
    }
    const float* brow = W + (size_t)k * ZD * CD + c16 * 4;

    const unsigned sA_b = (unsigned)__cvta_generic_to_shared(sA);
    const unsigned sB_b = (unsigned)__cvta_generic_to_shared(sB);
    const unsigned laneA = sA_b + (((mw + (lane & 15)) * SAS + ((lane >> 4) << 3)) << 1);
    const unsigned laneB = sB_b + ((((lane & 15)) * SAS + ((lane >> 4) << 3)) << 1);

    float acc[8][4];
#pragma unroll
    for (int j = 0; j < 8; j++)
#pragma unroll
        for (int i = 0; i < 4; i++) acc[j][i] = 0.f;

    for (int kk = 0; kk < CD; kk += CK) {
#pragma unroll
        for (int p = 0; p < 8; p++) {
            float4 v = *(const float4*)(arow[p] + kk);
            *(uint2*)&sA[(lr + 16 * p) * SAS + c16 * 4] = pack_h4(v);
        }
#pragma unroll
        for (int p = 0; p < 4; p++) {
            int n = lr + 16 * p;
            float4 v = *(const float4*)(brow + (size_t)n * CD + kk);
            *(uint2*)&sB[n * SAS + c16 * 4] = pack_h4(v);
        }
        __syncthreads();

#pragma unroll
        for (int ks = 0; ks < 4; ks++) {
            unsigned a[4];
            ldmx4(a, laneA + (ks << 5));
#pragma unroll
            for (int j2 = 0; j2 < 4; j2++) {
                unsigned bf[4];
                ldmx4(bf, laneB + (unsigned)(j2 * 16 * SAS * 2) + (ks << 5));
                mma16816(acc[2 * j2],     a, bf[0], bf[2]);
                mma16816(acc[2 * j2 + 1], a, bf[1], bf[3]);
            }
        }
        __syncthreads();
    }

    // ---------------- epilogue: bias + park Wc tile in smem ----------------
#pragma unroll
    for (int j = 0; j < 8; j++) {
        const int n = 8 * j + 2 * tig;
        float2 bb = *(const float2*)(bias + k * ZD + n);
        float2 o0, o1;
        o0.x = acc[j][0] + bb.x; o0.y = acc[j][1] + bb.y;
        o1.x = acc[j][2] + bb.x; o1.y = acc[j][3] + bb.y;
        *(float2*)(sWc + (size_t)(mw + grp) * WCSTR + n)     = o0;
        *(float2*)(sWc + (size_t)(mw + grp + 8) * WCSTR + n) = o1;
    }
    __syncthreads();

    // ---------------- scoring phase: quad-parallel, 4 rows/warp-iter -------
    const int quad = lane >> 3;             // 0..3 : which row of the group
    const int lq   = lane & 7;              // 0..7 : lane within quad (8 dims)

    const __half* zh_base = (const __half*)g_zh + lq * 8;   // row offset added per neg

    float warp_loss = 0.f, warp_acc = 0.f;  // valid at quad leaders (lq==0)

#pragma unroll
    for (int it = 0; it < 4; it++) {
        const int r  = mw + it * 4 + quad;
        const int m  = m0 + r;
        const int su = m / LEN;
        const int l  = m - su * LEN;
        const int s  = su >> 3;
        const int u  = su & 7;

        const float4* w4 = (const float4*)(sWc + (size_t)r * WCSTR + lq * 8);
        float4 w0 = w4[0], w1 = w4[1];

        const float4* zp = (const float4*)(z +
            (size_t)(su * T_ + (l + k + 1)) * ZD + lq * 8);
        float4 z0 = zp[0], z1 = zp[1];

        float p[18];
        {
            float sum = z0.x * w0.x;
            sum = fmaf(z0.y, w0.y, sum);
            sum = fmaf(z0.z, w0.z, sum);
            sum = fmaf(z0.w, w0.w, sum);
            sum = fmaf(z1.x, w1.x, sum);
            sum = fmaf(z1.y, w1.y, sum);
            sum = fmaf(z1.z, w1.z, sum);
            sum = fmaf(z1.w, w1.w, sum);
            p[0] = sum;
        }

        // preload + COMBINE indices: lane lq holds combined row-offsets for
        // n = lq, lq+8, lq+16:  off = (s*U+bn)*T + (k+1) + sn
        const int* bi = batch_index + (k * U_ + u) * NEG;
        const int* si = seq_index + ((size_t)((k * S_ + s) * U_ + u) * NEG) * LEN + l;
        const int srow = s * U_;
        int off_r[3];
#pragma unroll
        for (int j = 0; j < 3; j++) {
            int n = lq + 8 * j;
            if (n < NEG) {
                int bn = __ldg(bi + n);
                int sn = __ldg(si + (size_t)n * LEN);
                off_r[j] = (srow + bn) * T_ + (k + 1) + sn;
            } else off_r[j] = 0;
        }

#pragma unroll
        for (int n = 0; n < NEG; n++) {
            int off = __shfl_sync(0xffffffffu, off_r[n >> 3], n & 7, 8);
            const uint4* zn = (const uint4*)(zh_base + ((size_t)off << 6));
            uint4 raw = *zn;
            __half2 h0 = *(__half2*)&raw.x;
            __half2 h1 = *(__half2*)&raw.y;
            __half2 h2 = *(__half2*)&raw.z;
            __half2 h3 = *(__half2*)&raw.w;
            float2 a0 = __half22float2(h0);
            float2 a1 = __half22float2(h1);
            float2 a2 = __half22float2(h2);
            float2 a3 = __half22float2(h3);
            float sum = a0.x * w0.x;
            sum = fmaf(a0.y, w0.y, sum);
            sum = fmaf(a1.x, w0.z, sum);
            sum = fmaf(a1.y, w0.w, sum);
            sum = fmaf(a2.x, w1.x, sum);
            sum = fmaf(a2.y, w1.y, sum);
            sum = fmaf(a3.x, w1.z, sum);
            sum = fmaf(a3.y, w1.w, sum);
            p[1 + n] = sum;
        }

        // 3-round butterfly within each quad
#pragma unroll
        for (int off = 4; off >= 1; off >>= 1) {
#pragma unroll
            for (int n = 0; n < 18; n++)
                p[n] += __shfl_xor_sync(0xffffffffu, p[n], off);
        }

        if (lq == 0) {     // 4 quad leaders execute together
            float f0 = p[0] * 0.125f;
            float mxn = p[1];
#pragma unroll
            for (int n = 2; n < 18; n++) mxn = fmaxf(mxn, p[n]);
            mxn *= 0.125f;
            float mx = fmaxf(f0, mxn);
            float se = __expf(f0 - mx);
#pragma unroll
            for (int n = 1; n < 18; n++) se += __expf(p[n] * 0.125f - mx);
            warp_loss += (mx + __logf(se)) - f0;
            warp_acc  += (f0 >= mxn) ? 1.f : 0.f;   // argmax==0 (ties -> 0)
        }
    }

    warp_loss += __shfl_xor_sync(0xffffffffu, warp_loss, 8);
    warp_loss += __shfl_xor_sync(0xffffffffu, warp_loss, 16);
    warp_acc  += __shfl_xor_sync(0xffffffffu, warp_acc, 8);
    warp_acc  += __shfl_xor_sync(0xffffffffu, warp_acc, 16);

    if (lane == 0) {
        atomicAdd(&s_loss, warp_loss);
        atomicAdd(&s_acc, warp_acc);
    }
    __syncthreads();
    if (tid == 0) {
        atomicAdd(&g_loss_sum[k], s_loss);
        atomicAdd(&g_acc_sum[k], s_acc);
    }
}

// -------------------------------------------------------------------------
__global__ void finalize_kernel(float* __restrict__ out, int out_size) {
    __shared__ float sl[KSTEPS];
    int t = threadIdx.x;
    const float inv = 1.f / (float)(SU * LEN);
    if (t < KSTEPS) {
        sl[t] = g_loss_sum[t] * inv;
        if (1 + t < out_size) out[1 + t] = g_acc_sum[t] * inv;
    }
    __syncthreads();
    if (t == 0 && out_size > 0) {
        float sum = 0.f;
        for (int i = 0; i < KSTEPS; i++) sum += sl[i];
        out[0] = sum * (1.f / (float)KSTEPS);
    }
    for (int i = 13 + t; i < out_size; i += blockDim.x) out[i] = 0.f;
}

// -------------------------------------------------------------------------
extern "C" void kernel_launch(void* const* d_in, const int* in_sizes, int n_in,
                              void* d_out, int out_size) {
    const float* z           = (const float*)d_in[0];
    const float* c           = (const float*)d_in[1];
    const float* W           = (const float*)d_in[2];
    const float* b           = (const float*)d_in[3];
    const int*   batch_index = (const int*)d_in[4];
    const int*   seq_index   = (const int*)d_in[5];

    zero_sums_kernel<<<1, 32>>>();

    const size_t n4 = (size_t)SU * T_ * ZD / 4;
    convert_z_kernel<<<(unsigned)((n4 + 255) / 256), 256>>>(z);

    fused_kernel<<<NTILES * KSTEPS, 256>>>(z, c, W, b, batch_index, seq_index);
    finalize_kernel<<<1, 64>>>((float*)d_out, out_size);
}

// round 16
// speedup vs baseline: 1.3689x; 1.1313x over previous
#include <cuda_runtime.h>
#include <cuda_fp16.h>
#include <math.h>

// Problem constants
#define S_      8
#define U_      8
#define KSTEPS  12
#define NEG     17
#define ZD      64
#define CD      256
#define T_      1140
#define LEN     1128
#define SU      64              // S_*U_
#define MROWS   (SU*LEN)        // 72192
#define NTILES  (MROWS/128)     // 564
#define WCSTR   72              // smem Wc row stride (floats)
#define CK      64              // K-chunk (fp16 GEMM)
#define SAS     72              // smem A/B row stride in halves (144B: ldmatrix conflict-free)

__device__ float g_loss_sum[KSTEPS];
__device__ float g_acc_sum[KSTEPS];
__device__ __half g_zh[(size_t)SU * T_ * ZD];   // fp16 copy of z (9.3 MB)

// -------------------------------------------------------------------------
__global__ void zero_sums_kernel() {
    int t = threadIdx.x;
    if (t < KSTEPS) { g_loss_sum[t] = 0.f; g_acc_sum[t] = 0.f; }
}

// z -> fp16 (once per launch; deterministic)
__global__ void convert_z_kernel(const float* __restrict__ z) {
    size_t i = (size_t)blockIdx.x * blockDim.x + threadIdx.x;   // one float4
    const size_t n4 = (size_t)SU * T_ * ZD / 4;
    if (i < n4) {
        float4 v = ((const float4*)z)[i];
        __half2 h0 = __floats2half2_rn(v.x, v.y);
        __half2 h1 = __floats2half2_rn(v.z, v.w);
        uint2 o;
        o.x = *(unsigned*)&h0;
        o.y = *(unsigned*)&h1;
        ((uint2*)g_zh)[i] = o;
    }
}

// -------------------------------------------------------------------------
__device__ __forceinline__ uint2 pack_h4(float4 v) {
    __half2 h0 = __floats2half2_rn(v.x, v.y);
    __half2 h1 = __floats2half2_rn(v.z, v.w);
    uint2 o;
    o.x = *(unsigned*)&h0;
    o.y = *(unsigned*)&h1;
    return o;
}

__device__ __forceinline__ void ldmx4(unsigned* r, unsigned addr) {
    asm volatile("ldmatrix.sync.aligned.m8n8.x4.shared.b16 {%0,%1,%2,%3}, [%4];"
                 : "=r"(r[0]), "=r"(r[1]), "=r"(r[2]), "=r"(r[3]) : "r"(addr));
}

__device__ __forceinline__ void mma16816(float* c, const unsigned* a,
                                         unsigned b0, unsigned b1) {
    asm volatile(
        "mma.sync.aligned.m16n8k16.row.col.f32.f16.f16.f32 "
        "{%0,%1,%2,%3}, {%4,%5,%6,%7}, {%8,%9}, {%0,%1,%2,%3};\n"
        : "+f"(c[0]), "+f"(c[1]), "+f"(c[2]), "+f"(c[3])
        : "r"(a[0]), "r"(a[1]), "r"(a[2]), "r"(a[3]), "r"(b0), "r"(b1));
}

// fp16 row (uint4) dot fp32 weights
__device__ __forceinline__ float dot_h8(uint4 raw, float4 w0, float4 w1) {
    __half2 h0 = *(__half2*)&raw.x;
    __half2 h1 = *(__half2*)&raw.y;
    __half2 h2 = *(__half2*)&raw.z;
    __half2 h3 = *(__half2*)&raw.w;
    float2 a0 = __half22float2(h0);
    float2 a1 = __half22float2(h1);
    float2 a2 = __half22float2(h2);
    float2 a3 = __half22float2(h3);
    float sum = a0.x * w0.x;
    sum = fmaf(a0.y, w0.y, sum);
    sum = fmaf(a1.x, w0.z, sum);
    sum = fmaf(a1.y, w0.w, sum);
    sum = fmaf(a2.x, w1.x, sum);
    sum = fmaf(a2.y, w1.y, sum);
    sum = fmaf(a3.x, w1.z, sum);
    sum = fmaf(a3.y, w1.w, sum);
    return sum;
}

// -------------------------------------------------------------------------
// Fused: per CTA one 128x64 Wc tile (fp16 ldmatrix mma) -> smem, then
// quad-parallel scoring. R16: packed-exchange reduction (18->9->5->3),
// distributed logsumexp, pos row from fp16 copy.
__global__ __launch_bounds__(256, 2)
void fused_kernel(const float* __restrict__ z,
                  const float* __restrict__ c,
                  const float* __restrict__ W,
                  const float* __restrict__ bias,
                  const int* __restrict__ batch_index,
                  const int* __restrict__ seq_index) {
    __shared__ __align__(16) char smem_u[128 * WCSTR * 4];   // 36864 B union
    __shared__ float s_loss, s_acc;

    __half* sA  = (__half*)smem_u;          // [128][SAS] = 18432 B
    __half* sB  = sA + 128 * SAS;           // [64][SAS]  =  9216 B
    float*  sWc = (float*)smem_u;           // [128][WCSTR] overlays later

    const int bx = blockIdx.x;
    const int k  = bx % KSTEPS;             // k fastest -> c tile L2 reuse
    const int m0 = (bx / KSTEPS) * 128;

    const int tid  = threadIdx.x;
    const int warp = tid >> 5;
    const int lane = tid & 31;
    const int grp  = lane >> 2;             // 0..7 (mma C rows)
    const int tig  = lane & 3;              // 0..3
    const int mw   = warp * 16;

    if (tid == 0) { s_loss = 0.f; s_acc = 0.f; }

    // ---------------- GEMM phase (fp16 ldmatrix + mma.m16n8k16) ------------
    const int lr  = tid >> 4;               // 0..15 loader row-in-pass
    const int c16 = tid & 15;               // float4 col within 64-wide chunk

    const float* arow[8];
#pragma unroll
    for (int p = 0; p < 8; p++) {
        int m  = m0 + lr + 16 * p;
        int su = m / LEN;
        int l  = m - su * LEN;
        arow[p] = c + ((size_t)(su * T_ + l)) * CD + c16 * 4;
    }
    const float* brow = W + (size_t)k * ZD * CD + c16 * 4;

    const unsigned sA_b = (unsigned)__cvta_generic_to_shared(sA);
    const unsigned sB_b = (unsigned)__cvta_generic_to_shared(sB);
    const unsigned laneA = sA_b + (((mw + (lane & 15)) * SAS + ((lane >> 4) << 3)) << 1);
    const unsigned laneB = sB_b + ((((lane & 15)) * SAS + ((lane >> 4) << 3)) << 1);

    float acc[8][4];
#pragma unroll
    for (int j = 0; j < 8; j++)
#pragma unroll
        for (int i = 0; i < 4; i++) acc[j][i] = 0.f;

    for (int kk = 0; kk < CD; kk += CK) {
#pragma unroll
        for (int p = 0; p < 8; p++) {
            float4 v = *(const float4*)(arow[p] + kk);
            *(uint2*)&sA[(lr + 16 * p) * SAS + c16 * 4] = pack_h4(v);
        }
#pragma unroll
        for (int p = 0; p < 4; p++) {
            int n = lr + 16 * p;
            float4 v = *(const float4*)(brow + (size_t)n * CD + kk);
            *(uint2*)&sB[n * SAS + c16 * 4] = pack_h4(v);
        }
        __syncthreads();

#pragma unroll
        for (int ks = 0; ks < 4; ks++) {
            unsigned a[4];
            ldmx4(a, laneA + (ks << 5));
#pragma unroll
            for (int j2 = 0; j2 < 4; j2++) {
                unsigned bf[4];
                ldmx4(bf, laneB + (unsigned)(j2 * 16 * SAS * 2) + (ks << 5));
                mma16816(acc[2 * j2],     a, bf[0], bf[2]);
                mma16816(acc[2 * j2 + 1], a, bf[1], bf[3]);
            }
        }
        __syncthreads();
    }

    // ---------------- epilogue: bias + park Wc tile in smem ----------------
#pragma unroll
    for (int j = 0; j < 8; j++) {
        const int n = 8 * j + 2 * tig;
        float2 bb = *(const float2*)(bias + k * ZD + n);
        float2 o0, o1;
        o0.x = acc[j][0] + bb.x; o0.y = acc[j][1] + bb.y;
        o1.x = acc[j][2] + bb.x; o1.y = acc[j][3] + bb.y;
        *(float2*)(sWc + (size_t)(mw + grp) * WCSTR + n)     = o0;
        *(float2*)(sWc + (size_t)(mw + grp + 8) * WCSTR + n) = o1;
    }
    __syncthreads();

    // ---------------- scoring phase ----------------------------------------
    const int quad = lane >> 3;             // 0..3 : which row of the group
    const int lq   = lane & 7;              // 0..7 : lane within quad (8 dims)
    const bool lo4 = (lq & 4) == 0;
    const bool lo2 = (lq & 2) == 0;
    const bool lo1 = (lq & 1) == 0;

    const __half* zh_base = (const __half*)g_zh + lq * 8;

    float warp_loss = 0.f, warp_acc = 0.f;  // valid at quad leaders (lq==0)

#pragma unroll
    for (int it = 0; it < 4; it++) {
        const int r  = mw + it * 4 + quad;
        const int m  = m0 + r;
        const int su = m / LEN;
        const int l  = m - su * LEN;
        const int s  = su >> 3;
        const int u  = su & 7;

        const float4* w4 = (const float4*)(sWc + (size_t)r * WCSTR + lq * 8);
        float4 w0 = w4[0], w1 = w4[1];

        float p[18];
        // positive row from fp16 copy (1 LDG.128 per lane)
        {
            uint4 raw = *(const uint4*)(zh_base +
                ((size_t)(su * T_ + (l + k + 1)) << 6));
            p[0] = dot_h8(raw, w0, w1);
        }

        // preload + combine indices: lane lq holds combined row offsets for
        // n = lq, lq+8, lq+16 : off = (s*U+bn)*T + (k+1) + sn
        const int* bi = batch_index + (k * U_ + u) * NEG;
        const int* si = seq_index + ((size_t)((k * S_ + s) * U_ + u) * NEG) * LEN + l;
        const int srow = s * U_;
        int off_r[3];
#pragma unroll
        for (int j = 0; j < 3; j++) {
            int n = lq + 8 * j;
            if (n < NEG) {
                int bn = __ldg(bi + n);
                int sn = __ldg(si + (size_t)n * LEN);
                off_r[j] = (srow + bn) * T_ + (k + 1) + sn;
            } else off_r[j] = 0;
        }

#pragma unroll
        for (int n = 0; n < NEG; n++) {
            int off = __shfl_sync(0xffffffffu, off_r[n >> 3], n & 7, 8);
            uint4 raw = *(const uint4*)(zh_base + ((size_t)off << 6));
            p[1 + n] = dot_h8(raw, w0, w1);
        }

        // ---- packed-exchange reduction over the 8 quad lanes ----
        // R1 (offset 4): 18 -> 9.  lo4 keeps n=0..8, hi4 keeps n=9..17.
        float q[9];
#pragma unroll
        for (int j = 0; j < 9; j++) {
            float snd = lo4 ? p[9 + j] : p[j];
            float rcv = __shfl_xor_sync(0xffffffffu, snd, 4);
            q[j] = (lo4 ? p[j] : p[9 + j]) + rcv;
        }
        // R2 (offset 2): 9 -> 5/4. lo2 keeps q[0..4], hi2 keeps q[5..8].
        float r5[5];
#pragma unroll
        for (int j = 0; j < 4; j++) {
            float snd = lo2 ? q[5 + j] : q[j];
            float rcv = __shfl_xor_sync(0xffffffffu, snd, 2);
            r5[j] = (lo2 ? q[j] : q[5 + j]) + rcv;
        }
        {
            float rcv = __shfl_xor_sync(0xffffffffu, q[4], 2);
            r5[4] = q[4] + rcv;     // valid on lo2 lanes (5th value)
        }
        // R3 (offset 1): lo2 lanes 5 -> 3/2; hi2 lanes 4 -> 2/2.
        float g0, g1, g2;
        {
            float hi_a = lo2 ? r5[3] : r5[2];   // my "high" slot 0
            float hi_b = lo2 ? r5[4] : r5[3];   // my "high" slot 1
            float s0 = lo1 ? hi_a : r5[0];
            float t0 = __shfl_xor_sync(0xffffffffu, s0, 1);
            g0 = (lo1 ? r5[0] : hi_a) + t0;
            float s1 = lo1 ? hi_b : r5[1];
            float t1 = __shfl_xor_sync(0xffffffffu, s1, 1);
            g1 = (lo1 ? r5[1] : hi_b) + t1;
            float t2 = __shfl_xor_sync(0xffffffffu, r5[2], 1);
            g2 = r5[2] + t2;        // valid only on lanes lq==0 and lq==4
        }
        // layout: lq0:{n0,n1,n2} lq1:{n3,n4} lq2:{n5,n6} lq3:{n7,n8}
        //         lq4:{n9,n10,n11} lq5:{n12,n13} lq6:{n14,n15} lq7:{n16,n17}

        // ---- distributed logsumexp / argmax ----
        const bool has3 = (lq & 3) == 0;    // lanes 0 and 4
        float v0 = g0 * 0.125f;
        float v1 = g1 * 0.125f;
        float v2 = g2 * 0.125f;             // garbage (finite) on !has3

        float f0 = __shfl_sync(0xffffffffu, v0, 0, 8);   // n=0 score

        // neg-max: lane 0 excludes v0 (=f0); lane 4 includes v2
        float lmax = (lq == 0) ? v1 : fmaxf(v0, v1);
        lmax = (lq == 0) ? fmaxf(lmax, v2)
                         : ((lq == 4) ? fmaxf(lmax, v2) : lmax);
#pragma unroll
        for (int off = 4; off >= 1; off >>= 1)
            lmax = fmaxf(lmax, __shfl_xor_sync(0xffffffffu, lmax, off));
        float mxn = lmax;
        float mx  = fmaxf(f0, mxn);

        // exp-sum over ALL 18 (incl pos on lane 0)
        float ls = __expf(v0 - mx) + __expf(v1 - mx);
        ls += has3 ? __expf(v2 - mx) : 0.f;
#pragma unroll
        for (int off = 4; off >= 1; off >>= 1)
            ls += __shfl_xor_sync(0xffffffffu, ls, off);

        if (lq == 0) {
            warp_loss += (mx + __logf(ls)) - f0;
            warp_acc  += (f0 >= mxn) ? 1.f : 0.f;
        }
    }

    warp_loss += __shfl_xor_sync(0xffffffffu, warp_loss, 8);
    warp_loss += __shfl_xor_sync(0xffffffffu, warp_loss, 16);
    warp_acc  += __shfl_xor_sync(0xffffffffu, warp_acc, 8);
    warp_acc  += __shfl_xor_sync(0xffffffffu, warp_acc, 16);

    if (lane == 0) {
        atomicAdd(&s_loss, warp_loss);
        atomicAdd(&s_acc, warp_acc);
    }
    __syncthreads();
    if (tid == 0) {
        atomicAdd(&g_loss_sum[k], s_loss);
        atomicAdd(&g_acc_sum[k], s_acc);
    }
}

// -------------------------------------------------------------------------
__global__ void finalize_kernel(float* __restrict__ out, int out_size) {
    __shared__ float sl[KSTEPS];
    int t = threadIdx.x;
    const float inv = 1.f / (float)(SU * LEN);
    if (t < KSTEPS) {
        sl[t] = g_loss_sum[t] * inv;
        if (1 + t < out_size) out[1 + t] = g_acc_sum[t] * inv;
    }
    __syncthreads();
    if (t == 0 && out_size > 0) {
        float sum = 0.f;
        for (int i = 0; i < KSTEPS; i++) sum += sl[i];
        out[0] = sum * (1.f / (float)KSTEPS);
    }
    for (int i = 13 + t; i < out_size; i += blockDim.x) out[i] = 0.f;
}

// -------------------------------------------------------------------------
extern "C" void kernel_launch(void* const* d_in, const int* in_sizes, int n_in,
                              void* d_out, int out_size) {
    const float* z           = (const float*)d_in[0];
    const float* c           = (const float*)d_in[1];
    const float* W           = (const float*)d_in[2];
    const float* b           = (const float*)d_in[3];
    const int*   batch_index = (const int*)d_in[4];
    const int*   seq_index   = (const int*)d_in[5];

    zero_sums_kernel<<<1, 32>>>();

    const size_t n4 = (size_t)SU * T_ * ZD / 4;
    convert_z_kernel<<<(unsigned)((n4 + 255) / 256), 256>>>(z);

    fused_kernel<<<NTILES * KSTEPS, 256>>>(z, c, W, b, batch_index, seq_index);
    finalize_kernel<<<1, 64>>>((float*)d_out, out_size);
}

// round 17
// speedup vs baseline: 1.3710x; 1.0016x over previous
#include <cuda_runtime.h>
#include <cuda_fp16.h>
#include <math.h>

// Problem constants
#define S_      8
#define U_      8
#define KSTEPS  12
#define NEG     17
#define ZD      64
#define CD      256
#define T_      1140
#define LEN     1128
#define SU      64              // S_*U_
#define MROWS   (SU*LEN)        // 72192
#define NTILES  (MROWS/128)     // 564
#define WCSTR   72              // smem Wc row stride (floats)
#define CK      64              // K-chunk (fp16 GEMM)
#define SAS     72              // smem A/B row stride in halves (144B: ldmatrix conflict-free)

__device__ float g_loss_sum[KSTEPS];
__device__ float g_acc_sum[KSTEPS];
__device__ __half g_zh[(size_t)SU * T_ * ZD];   // fp16 copy of z (9.3 MB)

// -------------------------------------------------------------------------
__global__ void zero_sums_kernel() {
    int t = threadIdx.x;
    if (t < KSTEPS) { g_loss_sum[t] = 0.f; g_acc_sum[t] = 0.f; }
}

// z -> fp16 (once per launch; deterministic)
__global__ void convert_z_kernel(const float* __restrict__ z) {
    size_t i = (size_t)blockIdx.x * blockDim.x + threadIdx.x;   // one float4
    const size_t n4 = (size_t)SU * T_ * ZD / 4;
    if (i < n4) {
        float4 v = ((const float4*)z)[i];
        __half2 h0 = __floats2half2_rn(v.x, v.y);
        __half2 h1 = __floats2half2_rn(v.z, v.w);
        uint2 o;
        o.x = *(unsigned*)&h0;
        o.y = *(unsigned*)&h1;
        ((uint2*)g_zh)[i] = o;
    }
}

// -------------------------------------------------------------------------
__device__ __forceinline__ uint2 pack_h4(float4 v) {
    __half2 h0 = __floats2half2_rn(v.x, v.y);
    __half2 h1 = __floats2half2_rn(v.z, v.w);
    uint2 o;
    o.x = *(unsigned*)&h0;
    o.y = *(unsigned*)&h1;
    return o;
}

__device__ __forceinline__ void ldmx4(unsigned* r, unsigned addr) {
    asm volatile("ldmatrix.sync.aligned.m8n8.x4.shared.b16 {%0,%1,%2,%3}, [%4];"
                 : "=r"(r[0]), "=r"(r[1]), "=r"(r[2]), "=r"(r[3]) : "r"(addr));
}

__device__ __forceinline__ void mma16816(float* c, const unsigned* a,
                                         unsigned b0, unsigned b1) {
    asm volatile(
        "mma.sync.aligned.m16n8k16.row.col.f32.f16.f16.f32 "
        "{%0,%1,%2,%3}, {%4,%5,%6,%7}, {%8,%9}, {%0,%1,%2,%3};\n"
        : "+f"(c[0]), "+f"(c[1]), "+f"(c[2]), "+f"(c[3])
        : "r"(a[0]), "r"(a[1]), "r"(a[2]), "r"(a[3]), "r"(b0), "r"(b1));
}

// fp16 row (uint4) dot fp32 weights
__device__ __forceinline__ float dot_h8(uint4 raw, float4 w0, float4 w1) {
    __half2 h0 = *(__half2*)&raw.x;
    __half2 h1 = *(__half2*)&raw.y;
    __half2 h2 = *(__half2*)&raw.z;
    __half2 h3 = *(__half2*)&raw.w;
    float2 a0 = __half22float2(h0);
    float2 a1 = __half22float2(h1);
    float2 a2 = __half22float2(h2);
    float2 a3 = __half22float2(h3);
    float sum = a0.x * w0.x;
    sum = fmaf(a0.y, w0.y, sum);
    sum = fmaf(a1.x, w0.z, sum);
    sum = fmaf(a1.y, w0.w, sum);
    sum = fmaf(a2.x, w1.x, sum);
    sum = fmaf(a2.y, w1.y, sum);
    sum = fmaf(a3.x, w1.z, sum);
    sum = fmaf(a3.y, w1.w, sum);
    return sum;
}

// -------------------------------------------------------------------------
// Fused: per CTA one 128x64 Wc tile (fp16 ldmatrix mma) -> smem, then
// quad-parallel scoring. R16: packed-exchange reduction (18->9->5->3),
// distributed logsumexp, pos row from fp16 copy.
__global__ __launch_bounds__(256, 2)
void fused_kernel(const float* __restrict__ z,
                  const float* __restrict__ c,
                  const float* __restrict__ W,
                  const float* __restrict__ bias,
                  const int* __restrict__ batch_index,
                  const int* __restrict__ seq_index) {
    __shared__ __align__(16) char smem_u[128 * WCSTR * 4];   // 36864 B union
    __shared__ float s_loss, s_acc;

    __half* sA  = (__half*)smem_u;          // [128][SAS] = 18432 B
    __half* sB  = sA + 128 * SAS;           // [64][SAS]  =  9216 B
    float*  sWc = (float*)smem_u;           // [128][WCSTR] overlays later

    const int bx = blockIdx.x;
    const int k  = bx % KSTEPS;             // k fastest -> c tile L2 reuse
    const int m0 = (bx / KSTEPS) * 128;

    const int tid  = threadIdx.x;
    const int warp = tid >> 5;
    const int lane = tid & 31;
    const int grp  = lane >> 2;             // 0..7 (mma C rows)
    const int tig  = lane & 3;              // 0..3
    const int mw   = warp * 16;

    if (tid == 0) { s_loss = 0.f; s_acc = 0.f; }

    // ---------------- GEMM phase (fp16 ldmatrix + mma.m16n8k16) ------------
    const int lr  = tid >> 4;               // 0..15 loader row-in-pass
    const int c16 = tid & 15;               // float4 col within 64-wide chunk

    const float* arow[8];
#pragma unroll
    for (int p = 0; p < 8; p++) {
        int m  = m0 + lr + 16 * p;
        int su = m / LEN;
        int l  = m - su * LEN;
        arow[p] = c + ((size_t)(su * T_ + l)) * CD + c16 * 4;
    }
    const float* brow = W + (size_t)k * ZD * CD + c16 * 4;

    const unsigned sA_b = (unsigned)__cvta_generic_to_shared(sA);
    const unsigned sB_b = (unsigned)__cvta_generic_to_shared(sB);
    const unsigned laneA = sA_b + (((mw + (lane & 15)) * SAS + ((lane >> 4) << 3)) << 1);
    const unsigned laneB = sB_b + ((((lane & 15)) * SAS + ((lane >> 4) << 3)) << 1);

    float acc[8][4];
#pragma unroll
    for (int j = 0; j < 8; j++)
#pragma unroll
        for (int i = 0; i < 4; i++) acc[j][i] = 0.f;

    for (int kk = 0; kk < CD; kk += CK) {
#pragma unroll
        for (int p = 0; p < 8; p++) {
            float4 v = *(const float4*)(arow[p] + kk);
            *(uint2*)&sA[(lr + 16 * p) * SAS + c16 * 4] = pack_h4(v);
        }
#pragma unroll
        for (int p = 0; p < 4; p++) {
            int n = lr + 16 * p;
            float4 v = *(const float4*)(brow + (size_t)n * CD + kk);
            *(uint2*)&sB[n * SAS + c16 * 4] = pack_h4(v);
        }
        __syncthreads();

#pragma unroll
        for (int ks = 0; ks < 4; ks++) {
            unsigned a[4];
            ldmx4(a, laneA + (ks << 5));
#pragma unroll
            for (int j2 = 0; j2 < 4; j2++) {
                unsigned bf[4];
                ldmx4(bf, laneB + (unsigned)(j2 * 16 * SAS * 2) + (ks << 5));
                mma16816(acc[2 * j2],     a, bf[0], bf[2]);
                mma16816(acc[2 * j2 + 1], a, bf[1], bf[3]);
            }
        }
        __syncthreads();
    }

    // ---------------- epilogue: bias + park Wc tile in smem ----------------
#pragma unroll
    for (int j = 0; j < 8; j++) {
        const int n = 8 * j + 2 * tig;
        float2 bb = *(const float2*)(bias + k * ZD + n);
        float2 o0, o1;
        o0.x = acc[j][0] + bb.x; o0.y = acc[j][1] + bb.y;
        o1.x = acc[j][2] + bb.x; o1.y = acc[j][3] + bb.y;
        *(float2*)(sWc + (size_t)(mw + grp) * WCSTR + n)     = o0;
        *(float2*)(sWc + (size_t)(mw + grp + 8) * WCSTR + n) = o1;
    }
    __syncthreads();

    // ---------------- scoring phase ----------------------------------------
    const int quad = lane >> 3;             // 0..3 : which row of the group
    const int lq   = lane & 7;              // 0..7 : lane within quad (8 dims)
    const bool lo4 = (lq & 4) == 0;
    const bool lo2 = (lq & 2) == 0;
    const bool lo1 = (lq & 1) == 0;

    const __half* zh_base = (const __half*)g_zh + lq * 8;

    float warp_loss = 0.f, warp_acc = 0.f;  // valid at quad leaders (lq==0)

#pragma unroll
    for (int it = 0; it < 4; it++) {
        const int r  = mw + it * 4 + quad;
        const int m  = m0 + r;
        const int su = m / LEN;
        const int l  = m - su * LEN;
        const int s  = su >> 3;
        const int u  = su & 7;

        const float4* w4 = (const float4*)(sWc + (size_t)r * WCSTR + lq * 8);
        float4 w0 = w4[0], w1 = w4[1];

        float p[18];
        // positive row from fp16 copy (1 LDG.128 per lane)
        {
            uint4 raw = *(const uint4*)(zh_base +
                ((size_t)(su * T_ + (l + k + 1)) << 6));
            p[0] = dot_h8(raw, w0, w1);
        }

        // preload + combine indices: lane lq holds combined row offsets for
        // n = lq, lq+8, lq+16 : off = (s*U+bn)*T + (k+1) + sn
        const int* bi = batch_index + (k * U_ + u) * NEG;
        const int* si = seq_index + ((size_t)((k * S_ + s) * U_ + u) * NEG) * LEN + l;
        const int srow = s * U_;
        int off_r[3];
#pragma unroll
        for (int j = 0; j < 3; j++) {
            int n = lq + 8 * j;
            if (n < NEG) {
                int bn = __ldg(bi + n);
                int sn = __ldg(si + (size_t)n * LEN);
                off_r[j] = (srow + bn) * T_ + (k + 1) + sn;
            } else off_r[j] = 0;
        }

#pragma unroll
        for (int n = 0; n < NEG; n++) {
            int off = __shfl_sync(0xffffffffu, off_r[n >> 3], n & 7, 8);
            uint4 raw = *(const uint4*)(zh_base + ((size_t)off << 6));
            p[1 + n] = dot_h8(raw, w0, w1);
        }

        // ---- packed-exchange reduction over the 8 quad lanes ----
        // R1 (offset 4): 18 -> 9.  lo4 keeps n=0..8, hi4 keeps n=9..17.
        float q[9];
#pragma unroll
        for (int j = 0; j < 9; j++) {
            float snd = lo4 ? p[9 + j] : p[j];
            float rcv = __shfl_xor_sync(0xffffffffu, snd, 4);
            q[j] = (lo4 ? p[j] : p[9 + j]) + rcv;
        }
        // R2 (offset 2): 9 -> 5/4. lo2 keeps q[0..4], hi2 keeps q[5..8].
        float r5[5];
#pragma unroll
        for (int j = 0; j < 4; j++) {
            float snd = lo2 ? q[5 + j] : q[j];
            float rcv = __shfl_xor_sync(0xffffffffu, snd, 2);
            r5[j] = (lo2 ? q[j] : q[5 + j]) + rcv;
        }
        {
            float rcv = __shfl_xor_sync(0xffffffffu, q[4], 2);
            r5[4] = q[4] + rcv;     // valid on lo2 lanes (5th value)
        }
        // R3 (offset 1): lo2 lanes 5 -> 3/2; hi2 lanes 4 -> 2/2.
        float g0, g1, g2;
        {
            float hi_a = lo2 ? r5[3] : r5[2];   // my "high" slot 0
            float hi_b = lo2 ? r5[4] : r5[3];   // my "high" slot 1
            float s0 = lo1 ? hi_a : r5[0];
            float t0 = __shfl_xor_sync(0xffffffffu, s0, 1);
            g0 = (lo1 ? r5[0] : hi_a) + t0;
            float s1 = lo1 ? hi_b : r5[1];
            float t1 = __shfl_xor_sync(0xffffffffu, s1, 1);
            g1 = (lo1 ? r5[1] : hi_b) + t1;
            float t2 = __shfl_xor_sync(0xffffffffu, r5[2], 1);
            g2 = r5[2] + t2;        // valid only on lanes lq==0 and lq==4
        }
        // layout: lq0:{n0,n1,n2} lq1:{n3,n4} lq2:{n5,n6} lq3:{n7,n8}
        //         lq4:{n9,n10,n11} lq5:{n12,n13} lq6:{n14,n15} lq7:{n16,n17}

        // ---- distributed logsumexp / argmax ----
        const bool has3 = (lq & 3) == 0;    // lanes 0 and 4
        float v0 = g0 * 0.125f;
        float v1 = g1 * 0.125f;
        float v2 = g2 * 0.125f;             // garbage (finite) on !has3

        float f0 = __shfl_sync(0xffffffffu, v0, 0, 8);   // n=0 score

        // neg-max: lane 0 excludes v0 (=f0); lane 4 includes v2
        float lmax = (lq == 0) ? v1 : fmaxf(v0, v1);
        lmax = (lq == 0) ? fmaxf(lmax, v2)
                         : ((lq == 4) ? fmaxf(lmax, v2) : lmax);
#pragma unroll
        for (int off = 4; off >= 1; off >>= 1)
            lmax = fmaxf(lmax, __shfl_xor_sync(0xffffffffu, lmax, off));
        float mxn = lmax;
        float mx  = fmaxf(f0, mxn);

        // exp-sum over ALL 18 (incl pos on lane 0)
        float ls = __expf(v0 - mx) + __expf(v1 - mx);
        ls += has3 ? __expf(v2 - mx) : 0.f;
#pragma unroll
        for (int off = 4; off >= 1; off >>= 1)
            ls += __shfl_xor_sync(0xffffffffu, ls, off);

        if (lq == 0) {
            warp_loss += (mx + __logf(ls)) - f0;
            warp_acc  += (f0 >= mxn) ? 1.f : 0.f;
        }
    }

    warp_loss += __shfl_xor_sync(0xffffffffu, warp_loss, 8);
    warp_loss += __shfl_xor_sync(0xffffffffu, warp_loss, 16);
    warp_acc  += __shfl_xor_sync(0xffffffffu, warp_acc, 8);
    warp_acc  += __shfl_xor_sync(0xffffffffu, warp_acc, 16);

    if (lane == 0) {
        atomicAdd(&s_loss, warp_loss);
        atomicAdd(&s_acc, warp_acc);
    }
    __syncthreads();
    if (tid == 0) {
        atomicAdd(&g_loss_sum[k], s_loss);
        atomicAdd(&g_acc_sum[k], s_acc);
    }
}

// -------------------------------------------------------------------------
__global__ void finalize_kernel(float* __restrict__ out, int out_size) {
    __shared__ float sl[KSTEPS];
    int t = threadIdx.x;
    const float inv = 1.f / (float)(SU * LEN);
    if (t < KSTEPS) {
        sl[t] = g_loss_sum[t] * inv;
        if (1 + t < out_size) out[1 + t] = g_acc_sum[t] * inv;
    }
    __syncthreads();
    if (t == 0 && out_size > 0) {
        float sum = 0.f;
        for (int i = 0; i < KSTEPS; i++) sum += sl[i];
        out[0] = sum * (1.f / (float)KSTEPS);
    }
    for (int i = 13 + t; i < out_size; i += blockDim.x) out[i] = 0.f;
}

// -------------------------------------------------------------------------
extern "C" void kernel_launch(void* const* d_in, const int* in_sizes, int n_in,
                              void* d_out, int out_size) {
    const float* z           = (const float*)d_in[0];
    const float* c           = (const float*)d_in[1];
    const float* W           = (const float*)d_in[2];
    const float* b           = (const float*)d_in[3];
    const int*   batch_index = (const int*)d_in[4];
    const int*   seq_index   = (const int*)d_in[5];

    zero_sums_kernel<<<1, 32>>>();

    const size_t n4 = (size_t)SU * T_ * ZD / 4;
    convert_z_kernel<<<(unsigned)((n4 + 255) / 256), 256>>>(z);

    fused_kernel<<<NTILES * KSTEPS, 256>>>(z, c, W, b, batch_index, seq_index);
    finalize_kernel<<<1, 64>>>((float*)d_out, out_size);
}